// round 16
// baseline (speedup 1.0000x reference)
#include <cuda_runtime.h>
#include <cstdint>

#define NSAMP 256000
#define BATCH 64
#define NCHUNK 2
#define CHB (BATCH / NCHUNK)    // 32 batches per chunk
#define TT 997
#define BT (BATCH * TT)         // 63808
#define BTQ (CHB * TT)          // 31904
#define NFREQ 513
#define MAGP 528                // mag padded stride (33*16)
#define KSPEC 1040              // spec/gmat padded stride (65*16), data cols 0..1025
#define ENCD 256
#define EPS32 1.1920928955078125e-07f
#define PI_F 3.14159265358979323846f

// ---------------- scratch (device globals; allocation-free rule; zero-initialized) ------
__device__ float g_mag [(size_t)BT * MAGP];
__device__ float g_Rm  [(size_t)BT * NFREQ];
__device__ float g_Imb [(size_t)BT * NFREQ];
__device__ float g_xg  [(size_t)BT * 512];
__device__ float g_h1  [(size_t)BT * 128];
__device__ float g_h2  [(size_t)BT * 128];
__device__ float g_spec[(size_t)BT * KSPEC];   // [Sr(513) | Si(513) | pad] per row
__device__ float g_enc [(size_t)BT * ENCD];
__device__ float g_encn[(size_t)BT * ENCD];
__device__ float g_m2e [(size_t)BT * ENCD];
__device__ float g_dec [(size_t)BT * 1024];
__device__ float g_w1p [512 * MAGP];
__device__ float g_gmat[256 * KSPEC];          // [w*Gr/1024 | w*Gi/1024 | 0] per enc row

// ---------------- streams/events (created at load, before harness baseline) -------------
struct GpuCtx {
    cudaStream_t s1;
    cudaEvent_t e_stag, e_join;
    GpuCtx() {
        cudaStreamCreateWithFlags(&s1, cudaStreamNonBlocking);
        cudaEventCreateWithFlags(&e_stag, cudaEventDisableTiming);
        cudaEventCreateWithFlags(&e_join, cudaEventDisableTiming);
    }
};
static GpuCtx g_ctx;

__device__ __forceinline__ float sigm(float x) { return 1.0f / (1.0f + __expf(-x)); }
__device__ __forceinline__ float tanh_f(float x) { return 2.0f / (1.0f + __expf(-2.0f * x)) - 1.0f; }

// ---------------- cp.async helpers ----------------
__device__ __forceinline__ void cp16(uint32_t dst, const void* src) {
    asm volatile("cp.async.cg.shared.global [%0], [%1], 16;" :: "r"(dst), "l"(src));
}
#define CP_COMMIT() asm volatile("cp.async.commit_group;" ::: "memory")
#define CP_WAIT(n)  asm volatile("cp.async.wait_group %0;" :: "n"(n) : "memory")

// ---------------- 3xTF32 split: f = hi + lo, both tf32 (rna) ----------------
__device__ __forceinline__ void tf32split(float f, uint32_t& hi, uint32_t& lo) {
    uint32_t h;
    asm("cvt.rna.tf32.f32 %0, %1;" : "=r"(h) : "f"(f));
    float r = f - __uint_as_float(h);
    asm("cvt.rna.tf32.f32 %0, %1;" : "=r"(lo) : "f"(r));
    hi = h;
}
__device__ __forceinline__ void mma8(float* c, const uint32_t* a, const uint32_t* b) {
    asm volatile(
        "mma.sync.aligned.m16n8k8.row.col.f32.tf32.tf32.f32 "
        "{%0,%1,%2,%3}, {%4,%5,%6,%7}, {%8,%9}, {%0,%1,%2,%3};"
        : "+f"(c[0]), "+f"(c[1]), "+f"(c[2]), "+f"(c[3])
        : "r"(a[0]), "r"(a[1]), "r"(a[2]), "r"(a[3]), "r"(b[0]), "r"(b[1]));
}

// ---------------- packed f32x2 fma ----------------
__device__ __forceinline__ unsigned long long fma2(unsigned long long a, unsigned long long b,
                                                   unsigned long long c) {
    unsigned long long d;
    asm("fma.rn.f32x2 %0, %1, %2, %3;" : "=l"(d) : "l"(a), "l"(b), "l"(c));
    return d;
}

// ---------------- 3xTF32 tensor-core GEMM (r10 shape): C[M,N] = A[M,K] @ W[N,K]^T -------
// MODE 0: + b1 + b2 (nullable). MODE 1: sigmoid(+b1). MODE 2: sigmoid(+b1)*aux[m,n].
// MODE 3: v=sigmoid(+b1); C[m,n]=v*aux[m,n]; C[m,513+n]=v*aux2[m,n]  (masked spectrum)
#define SSTRIDE 20
template<int MODE>
__global__ void __launch_bounds__(256) gemm_mma(
    const float* __restrict__ A, const float* __restrict__ W,
    const float* __restrict__ b1, const float* __restrict__ b2,
    const float* __restrict__ aux, const float* __restrict__ aux2,
    float* __restrict__ C,
    int M, int N, int K, int lda, int ldw, int ldc, int ldaux)
{
    __shared__ float As[2][128 * SSTRIDE];
    __shared__ float Bs[2][128 * SSTRIDE];
    int tid = threadIdx.x;
    int lane = tid & 31;
    int wid = tid >> 5;
    int wm = wid & 3;
    int wn = wid >> 2;
    int m0 = blockIdx.x * 128, n0 = blockIdx.y * 128;

    int lr = tid >> 1;
    int lc0 = (tid & 1) * 2;
    const float* Arow = A + (size_t)min(m0 + lr, M - 1) * lda;
    const float* Wrow = W + (size_t)min(n0 + lr, N - 1) * ldw;

    uint32_t sA0 = (uint32_t)__cvta_generic_to_shared(&As[0][0]);
    uint32_t sB0 = (uint32_t)__cvta_generic_to_shared(&Bs[0][0]);
    const uint32_t stageBytes = 128 * SSTRIDE * 4;
    uint32_t dstOffA = (lr * SSTRIDE + lc0 * 4) * 4;

    #define LOAD_STAGE(t, s) do { \
        uint32_t dA = sA0 + (s) * stageBytes + dstOffA; \
        uint32_t dB = sB0 + (s) * stageBytes + dstOffA; \
        int f0 = (t) * 16 + lc0 * 4; \
        cp16(dA,      Arow + f0); \
        cp16(dA + 16, Arow + f0 + 4); \
        cp16(dB,      Wrow + f0); \
        cp16(dB + 16, Wrow + f0 + 4); \
        CP_COMMIT(); \
    } while (0)

    float c[2][8][4];
    #pragma unroll
    for (int mi = 0; mi < 2; mi++)
        #pragma unroll
        for (int j = 0; j < 8; j++)
            #pragma unroll
            for (int r = 0; r < 4; r++) c[mi][j][r] = 0.0f;

    const int NT = K >> 4;
    LOAD_STAGE(0, 0);

    int aoff0 = (wm * 32 + (lane >> 2)) * SSTRIDE + (lane & 3);
    int boff0 = (wn * 64 + (lane >> 2)) * SSTRIDE + (lane & 3);

    for (int t = 0; t < NT; t++) {
        int buf = t & 1;
        if (t + 1 < NT) {
            LOAD_STAGE(t + 1, (t + 1) & 1);
            CP_WAIT(1);
        } else {
            CP_WAIT(0);
        }
        __syncthreads();

        const float* Sa = As[buf];
        const float* Sb = Bs[buf];
        #pragma unroll
        for (int kh = 0; kh < 2; kh++) {
            uint32_t ah[2][4], al[2][4];
            #pragma unroll
            for (int mi = 0; mi < 2; mi++) {
                int o = aoff0 + mi * 16 * SSTRIDE + kh * 8;
                tf32split(Sa[o],                   ah[mi][0], al[mi][0]);
                tf32split(Sa[o + 8 * SSTRIDE],     ah[mi][1], al[mi][1]);
                tf32split(Sa[o + 4],               ah[mi][2], al[mi][2]);
                tf32split(Sa[o + 8 * SSTRIDE + 4], ah[mi][3], al[mi][3]);
            }
            uint32_t bh[8][2], bl[8][2];
            #pragma unroll
            for (int j = 0; j < 8; j++) {
                int o = boff0 + j * 8 * SSTRIDE + kh * 8;
                tf32split(Sb[o],     bh[j][0], bl[j][0]);
                tf32split(Sb[o + 4], bh[j][1], bl[j][1]);
            }
            #pragma unroll
            for (int mi = 0; mi < 2; mi++)
                #pragma unroll
                for (int j = 0; j < 8; j++) {
                    mma8(c[mi][j], ah[mi], bl[j]);
                    mma8(c[mi][j], al[mi], bh[j]);
                    mma8(c[mi][j], ah[mi], bh[j]);
                }
        }
        __syncthreads();
    }

    #pragma unroll
    for (int mi = 0; mi < 2; mi++) {
        #pragma unroll
        for (int rh = 0; rh < 2; rh++) {
            int m = m0 + wm * 32 + mi * 16 + (lane >> 2) + rh * 8;
            if (m >= M) continue;
            float* crow = C + (size_t)m * ldc;
            const float* arow  = (MODE >= 2) ? aux  + (size_t)m * ldaux : nullptr;
            const float* arow2 = (MODE == 3) ? aux2 + (size_t)m * ldaux : nullptr;
            #pragma unroll
            for (int j = 0; j < 8; j++) {
                int n = n0 + wn * 64 + j * 8 + 2 * (lane & 3);
                float v0 = c[mi][j][rh * 2];
                float v1 = c[mi][j][rh * 2 + 1];
                if (MODE == 0) {
                    if (b1) { v0 += __ldg(&b1[n]); v1 += __ldg(&b1[n + 1]); }
                    if (b2) { v0 += __ldg(&b2[n]); v1 += __ldg(&b2[n + 1]); }
                    if (n < N)     crow[n]     = v0;
                    if (n + 1 < N) crow[n + 1] = v1;
                } else if (MODE == 1) {
                    if (n < N)     crow[n]     = sigm(v0 + __ldg(&b1[n]));
                    if (n + 1 < N) crow[n + 1] = sigm(v1 + __ldg(&b1[n + 1]));
                } else if (MODE == 2) {
                    if (n < N)     crow[n]     = sigm(v0 + __ldg(&b1[n]))     * arow[n];
                    if (n + 1 < N) crow[n + 1] = sigm(v1 + __ldg(&b1[n + 1])) * arow[n + 1];
                } else {
                    if (n < N) {
                        float s0 = sigm(v0 + __ldg(&b1[n]));
                        crow[n]       = s0 * arow[n];
                        crow[513 + n] = s0 * arow2[n];
                    }
                    if (n + 1 < N) {
                        float s1 = sigm(v1 + __ldg(&b1[n + 1]));
                        crow[n + 1]       = s1 * arow[n + 1];
                        crow[513 + n + 1] = s1 * arow2[n + 1];
                    }
                }
            }
        }
    }
    #undef LOAD_STAGE
}

// ---------------- weight pack: s1_Wih1 [512,513] -> [512,528] zero-padded ----------------
__global__ void pack_w1(const float* __restrict__ w, float* __restrict__ out) {
    int i = blockIdx.x * 256 + threadIdx.x;
    if (i < 512 * MAGP) {
        int r = i / MAGP, c = i - r * MAGP;
        out[i] = (c < NFREQ) ? w[r * NFREQ + c] : 0.0f;
    }
}

// ---------------- 512-pt complex Stockham FFT (table-driven twiddles) ----------------
__device__ __forceinline__ void build_tw(float2* tw, int tid, int nthr) {
    for (int m = tid; m <= 512; m += nthr) {
        float s, c;
        __sincosf(PI_F * (float)m * (1.0f / 512.0f), &s, &c);
        tw[m] = make_float2(c, -s);
    }
}
__device__ __forceinline__ float2* fft512(float2* a, float2* b, const float2* tw,
                                          bool fwd, int tid) {
    float2* src = a; float2* dst = b;
    #pragma unroll
    for (int s = 0; s < 9; s++) {
        int m = 1 << s;
        int j = tid >> s;
        int k = tid & (m - 1);
        float2 w = tw[j << (s + 1)];
        float wc = w.x;
        float ws = fwd ? w.y : -w.y;
        float2 c0 = src[tid];
        float2 c1 = src[tid + 256];
        float2 dif = make_float2(c0.x - c1.x, c0.y - c1.y);
        dst[2 * j * m + k]     = make_float2(c0.x + c1.x, c0.y + c1.y);
        dst[2 * j * m + k + m] = make_float2(wc * dif.x - ws * dif.y, wc * dif.y + ws * dif.x);
        __syncthreads();
        float2* t = src; src = dst; dst = t;
    }
    return src;
}

// ---------------- STFT (chunk of CHB batches) ----------------
__global__ void stft_kernel(const float* __restrict__ x, float* __restrict__ mag,
                            float* __restrict__ Rm, float* __restrict__ Imb) {
    __shared__ float2 za[512], zb[512];
    __shared__ float2 tw[513];
    int bt = blockIdx.x;
    int b = bt / TT, t = bt - b * TT;
    const float* xp = x + (size_t)b * NSAMP + t * 256;
    int tid = threadIdx.x;
    build_tw(tw, tid, 256);
    __syncthreads();
    for (int n = tid; n < 512; n += 256) {
        int i0 = 2 * n, i1 = 2 * n + 1;
        float c0 = tw[(i0 <= 512) ? i0 : 1024 - i0].x;
        float c1 = tw[(i1 <= 512) ? i1 : 1024 - i1].x;
        za[n] = make_float2(xp[i0] * (0.5f * (1.0f - c0)), xp[i1] * (0.5f * (1.0f - c1)));
    }
    __syncthreads();
    float2* Z = fft512(za, zb, tw, true, tid);
    size_t baseM = (size_t)bt * MAGP;
    size_t base = (size_t)bt * NFREQ;
    for (int k = tid; k <= 512; k += 256) {
        float2 zk = Z[k & 511];
        float2 zc = Z[(512 - k) & 511];
        float Er = 0.5f * (zk.x + zc.x), Ei = 0.5f * (zk.y - zc.y);
        float Or = 0.5f * (zk.y + zc.y), Oi = -0.5f * (zk.x - zc.x);
        float2 w = tw[k];
        float wc = w.x, ws = w.y;
        float Xr = Er + wc * Or - ws * Oi;
        float Xi = Ei + wc * Oi + ws * Or;
        float mg = sqrtf(fmaxf(Xr * Xr + Xi * Xi, EPS32));
        float rp = Xr + EPS32, ip = Xi + EPS32;
        float inv = rsqrtf(rp * rp + ip * ip);
        mag[baseM + k] = mg;
        Rm[base + k]   = mg * rp * inv;
        Imb[base + k]  = mg * ip * inv;
    }
    if (tid < MAGP - NFREQ) mag[baseM + NFREQ + tid] = 0.0f;
}

// ---------------- G-matrix precompute: gmat[e,:] = [w*Gr/1024 | w*Gi/1024 | 0] ----------
__global__ void prep_gmat(const float* __restrict__ encW, float* __restrict__ gmat) {
    __shared__ float2 za[512], zb[512];
    __shared__ float2 tw[513];
    int e = blockIdx.x;
    int tid = threadIdx.x;
    const float* wr = encW + (size_t)e * 1024;
    build_tw(tw, tid, 256);
    for (int n = tid; n < 512; n += 256)
        za[n] = make_float2(wr[2 * n], wr[2 * n + 1]);
    __syncthreads();
    float2* Z = fft512(za, zb, tw, true, tid);
    float* grow = gmat + (size_t)e * KSPEC;
    for (int k = tid; k <= 512; k += 256) {
        float2 zk = Z[k & 511];
        float2 zc = Z[(512 - k) & 511];
        float Er = 0.5f * (zk.x + zc.x), Ei = 0.5f * (zk.y - zc.y);
        float Or = 0.5f * (zk.y + zc.y), Oi = -0.5f * (zk.x - zc.x);
        float2 w = tw[k];
        float wc = w.x, ws = w.y;
        float Gr = Er + wc * Or - ws * Oi;
        float Gi = Ei + wc * Oi + ws * Or;
        float scale = ((k == 0) || (k == 512)) ? (1.0f / 1024.0f) : (2.0f / 1024.0f);
        grow[k]       = Gr * scale;
        grow[513 + k] = Gi * scale;
    }
    if (tid < KSPEC - 1026) grow[1026 + tid] = 0.0f;
}

// ---------------- LSTM scan (chunk): quad-gate, f32x2 FMA, 96 weight cols in regs -------
__global__ void __launch_bounds__(512) lstm_kernel(
    const float* __restrict__ xg, float* __restrict__ hout,
    const float* __restrict__ Whh, const float* __restrict__ state, int layer, int b0) {
    extern __shared__ float sm[];
    ulonglong2* Wsm = (ulonglong2*)sm;       // [8][512]: cols 96..127
    float* h_s = sm + 8 * 512 * 4;           // 2 x 128 floats (ping-pong)
    int b = blockIdx.x, t = threadIdx.x;
    int cell = t >> 2, gate = t & 3;
    int row = gate * 128 + cell;
    const unsigned long long* wr8 = (const unsigned long long*)(Whh + (size_t)row * 128);
    unsigned long long w2[48];
    #pragma unroll
    for (int p = 0; p < 48; p++) w2[p] = __ldg(&wr8[p]);
    #pragma unroll
    for (int g = 0; g < 8; g++) {
        const ulonglong2* p = (const ulonglong2*)(Whh + (size_t)row * 128 + 96 + g * 4);
        Wsm[g * 512 + t] = *p;
    }
    float cv;
    {
        size_t sb = ((size_t)(layer * BATCH + b0 + b) * 128 + cell) * 2;
        cv = state[sb + 1];
        if (gate == 0) h_s[cell] = state[sb];
    }
    __syncthreads();
    const float* xr = xg + (size_t)b * TT * 512 + row;
    float* hr = hout + (size_t)b * TT * 128;
    int lane = t & 31;
    int q = lane & ~3;
    float xcur = __ldg(xr);
    for (int tt = 0; tt < TT; tt++) {
        float xnext = (tt + 1 < TT) ? __ldg(xr + (tt + 1) * 512) : 0.0f;
        const ulonglong2* h2 = (const ulonglong2*)(h_s + (tt & 1) * 128);
        unsigned long long acc0, acc1;
        asm("mov.b64 %0, {%1,%2};" : "=l"(acc0) : "f"(xcur), "f"(0.0f));
        asm("mov.b64 %0, {%1,%2};" : "=l"(acc1) : "f"(0.0f), "f"(0.0f));
        #pragma unroll
        for (int g = 0; g < 24; g++) {
            ulonglong2 hv = h2[g];
            acc0 = fma2(w2[2 * g],     hv.x, acc0);
            acc1 = fma2(w2[2 * g + 1], hv.y, acc1);
        }
        #pragma unroll
        for (int g = 0; g < 8; g++) {
            ulonglong2 wv = Wsm[g * 512 + t];
            ulonglong2 hv = h2[24 + g];
            acc0 = fma2(wv.x, hv.x, acc0);
            acc1 = fma2(wv.y, hv.y, acc1);
        }
        float a0, a1, a2, a3;
        asm("mov.b64 {%0,%1}, %2;" : "=f"(a0), "=f"(a1) : "l"(acc0));
        asm("mov.b64 {%0,%1}, %2;" : "=f"(a2), "=f"(a3) : "l"(acc1));
        float acc = (a0 + a2) + (a1 + a3);
        float v = (gate == 2) ? tanh_f(acc) : sigm(acc);
        float iv = __shfl_sync(0xffffffffu, v, q + 0);
        float fv = __shfl_sync(0xffffffffu, v, q + 1);
        float gv = __shfl_sync(0xffffffffu, v, q + 2);
        float ov = __shfl_sync(0xffffffffu, v, q + 3);
        cv = fv * cv + iv * gv;
        float hv = ov * tanh_f(cv);
        if (gate == 0) {
            h_s[((tt + 1) & 1) * 128 + cell] = hv;
            hr[tt * 128 + cell] = hv;
        }
        __syncthreads();
        xcur = xnext;
    }
}

// ---------------- instant layernorm over last dim (256) ----------------
__global__ void iln_kernel(const float* __restrict__ enc, const float* __restrict__ gamma,
                           const float* __restrict__ beta, float* __restrict__ out) {
    int bt = blockIdx.x, tid = threadIdx.x;
    float v = enc[(size_t)bt * ENCD + tid];
    float s1 = v, s2 = v * v;
    #pragma unroll
    for (int o = 16; o > 0; o >>= 1) {
        s1 += __shfl_xor_sync(0xffffffff, s1, o);
        s2 += __shfl_xor_sync(0xffffffff, s2, o);
    }
    __shared__ float r1[8], r2[8];
    int wid = tid >> 5;
    if ((tid & 31) == 0) { r1[wid] = s1; r2[wid] = s2; }
    __syncthreads();
    if (tid == 0) {
        float a1 = 0.0f, a2 = 0.0f;
        #pragma unroll
        for (int i = 0; i < 8; i++) { a1 += r1[i]; a2 += r2[i]; }
        r1[0] = a1; r2[0] = a2;
    }
    __syncthreads();
    float mean = r1[0] * (1.0f / 256.0f);
    float var  = r2[0] * (1.0f / 256.0f) - mean * mean;
    out[(size_t)bt * ENCD + tid] =
        (v - mean) * rsqrtf(var + 1e-7f) * gamma[tid] + beta[tid];
}

// ---------------- overlap-add (chunk of CHB batches) ----------------
__global__ void ola_kernel(const float* __restrict__ dec, float* __restrict__ out) {
    int s = blockIdx.x * 256 + threadIdx.x;
    int b = blockIdx.y;
    int thi = min(TT - 1, s >> 8);
    int tlo = (s >= 1024) ? ((s - 1023 + 255) >> 8) : 0;
    float acc = 0.0f;
    for (int t = tlo; t <= thi; t++)
        acc += dec[((size_t)b * TT + t) * 1024 + (s - (t << 8))];
    out[(size_t)b * NSAMP + s] = acc;
}

// ---------------- host ----------------
extern "C" void kernel_launch(void* const* d_in, const int* in_sizes, int n_in,
                              void* d_out, int out_size) {
    const float* x        = (const float*)d_in[0];
    const float* st1      = (const float*)d_in[1];
    const float* st2      = (const float*)d_in[2];
    const float* s1_Wih1  = (const float*)d_in[3];
    const float* s1_Whh1  = (const float*)d_in[4];
    const float* s1_bih1  = (const float*)d_in[5];
    const float* s1_bhh1  = (const float*)d_in[6];
    const float* s1_Wih2  = (const float*)d_in[7];
    const float* s1_Whh2  = (const float*)d_in[8];
    const float* s1_bih2  = (const float*)d_in[9];
    const float* s1_bhh2  = (const float*)d_in[10];
    const float* s1_Wd    = (const float*)d_in[11];
    const float* s1_bd    = (const float*)d_in[12];
    const float* s2_Wih1  = (const float*)d_in[13];
    const float* s2_Whh1  = (const float*)d_in[14];
    const float* s2_bih1  = (const float*)d_in[15];
    const float* s2_bhh1  = (const float*)d_in[16];
    const float* s2_Wih2  = (const float*)d_in[17];
    const float* s2_Whh2  = (const float*)d_in[18];
    const float* s2_bih2  = (const float*)d_in[19];
    const float* s2_bhh2  = (const float*)d_in[20];
    const float* s2_Wd    = (const float*)d_in[21];
    const float* s2_bd    = (const float*)d_in[22];
    const float* enc_W    = (const float*)d_in[23];
    const float* dec_W    = (const float*)d_in[24];
    const float* gamma    = (const float*)d_in[25];
    const float* beta     = (const float*)d_in[26];
    float* out = (float*)d_out;

    float *mag, *Rm, *Imb, *xg, *h1, *h2, *spec, *enc, *encn, *m2e, *dec, *w1p, *gmat;
    cudaGetSymbolAddress((void**)&mag,   g_mag);
    cudaGetSymbolAddress((void**)&Rm,    g_Rm);
    cudaGetSymbolAddress((void**)&Imb,   g_Imb);
    cudaGetSymbolAddress((void**)&xg,    g_xg);
    cudaGetSymbolAddress((void**)&h1,    g_h1);
    cudaGetSymbolAddress((void**)&h2,    g_h2);
    cudaGetSymbolAddress((void**)&spec,  g_spec);
    cudaGetSymbolAddress((void**)&enc,   g_enc);
    cudaGetSymbolAddress((void**)&encn,  g_encn);
    cudaGetSymbolAddress((void**)&m2e,   g_m2e);
    cudaGetSymbolAddress((void**)&dec,   g_dec);
    cudaGetSymbolAddress((void**)&w1p,   g_w1p);
    cudaGetSymbolAddress((void**)&gmat,  g_gmat);

    const int LSTM_SMEM = 8 * 512 * 16 + 2 * 128 * 4;  // 66,560 B
    cudaFuncSetAttribute(lstm_kernel, cudaFuncAttributeMaxDynamicSharedMemorySize, LSTM_SMEM);

    const int MTQ = (BTQ + 127) / 128;  // 250

    // ---- shared prologue on origin stream ----
    pack_w1<<<(512 * MAGP + 255) / 256, 256>>>(s1_Wih1, w1p);
    prep_gmat<<<256, 256>>>(enc_W, gmat);

    for (int c = 0; c < NCHUNK; c++) {
        cudaStream_t st = (c == 0) ? (cudaStream_t)0 : g_ctx.s1;
        if (c == 1) cudaStreamWaitEvent(g_ctx.s1, g_ctx.e_stag, 0);  // anti-phase stagger
        int b0 = c * CHB;
        const float* xc = x + (size_t)b0 * NSAMP;
        float* magc   = mag   + (size_t)c * BTQ * MAGP;
        float* Rmc    = Rm    + (size_t)c * BTQ * NFREQ;
        float* Imc    = Imb   + (size_t)c * BTQ * NFREQ;
        float* xgc    = xg    + (size_t)c * BTQ * 512;
        float* h1c    = h1    + (size_t)c * BTQ * 128;
        float* h2c    = h2    + (size_t)c * BTQ * 128;
        float* specc  = spec  + (size_t)c * BTQ * KSPEC;
        float* encc   = enc   + (size_t)c * BTQ * ENCD;
        float* encnc  = encn  + (size_t)c * BTQ * ENCD;
        float* m2ec   = m2e   + (size_t)c * BTQ * ENCD;
        float* decc   = dec   + (size_t)c * BTQ * 1024;
        float* outc   = out   + (size_t)b0 * NSAMP;

        stft_kernel<<<BTQ, 256, 0, st>>>(xc, magc, Rmc, Imc);

        gemm_mma<0><<<dim3(MTQ, 4), 256, 0, st>>>(magc, w1p, s1_bih1, s1_bhh1, nullptr, nullptr,
            xgc, BTQ, 512, MAGP, MAGP, MAGP, 512, 0);
        lstm_kernel<<<CHB, 512, LSTM_SMEM, st>>>(xgc, h1c, s1_Whh1, st1, 0, b0);
        if (c == 0) cudaEventRecord(g_ctx.e_stag, (cudaStream_t)0);  // fires after L1(c0)
        gemm_mma<0><<<dim3(MTQ, 4), 256, 0, st>>>(h1c, s1_Wih2, s1_bih2, s1_bhh2, nullptr, nullptr,
            xgc, BTQ, 512, 128, 128, 128, 512, 0);
        lstm_kernel<<<CHB, 512, LSTM_SMEM, st>>>(xgc, h2c, s1_Whh2, st1, 1, b0);
        gemm_mma<3><<<dim3(MTQ, 5), 256, 0, st>>>(h2c, s1_Wd, s1_bd, nullptr, Rmc, Imc,
            specc, BTQ, NFREQ, 128, 128, 128, KSPEC, NFREQ);

        gemm_mma<0><<<dim3(MTQ, 2), 256, 0, st>>>(specc, gmat, nullptr, nullptr, nullptr, nullptr,
            encc, BTQ, ENCD, KSPEC, KSPEC, KSPEC, ENCD, 0);
        iln_kernel<<<BTQ, 256, 0, st>>>(encc, gamma, beta, encnc);

        gemm_mma<0><<<dim3(MTQ, 4), 256, 0, st>>>(encnc, s2_Wih1, s2_bih1, s2_bhh1, nullptr, nullptr,
            xgc, BTQ, 512, ENCD, ENCD, ENCD, 512, 0);
        lstm_kernel<<<CHB, 512, LSTM_SMEM, st>>>(xgc, h1c, s2_Whh1, st2, 0, b0);
        gemm_mma<0><<<dim3(MTQ, 4), 256, 0, st>>>(h1c, s2_Wih2, s2_bih2, s2_bhh2, nullptr, nullptr,
            xgc, BTQ, 512, 128, 128, 128, 512, 0);
        lstm_kernel<<<CHB, 512, LSTM_SMEM, st>>>(xgc, h2c, s2_Whh2, st2, 1, b0);
        gemm_mma<2><<<dim3(MTQ, 2), 256, 0, st>>>(h2c, s2_Wd, s2_bd, nullptr, encc, nullptr,
            m2ec, BTQ, ENCD, 128, 128, 128, ENCD, ENCD);

        gemm_mma<0><<<dim3(MTQ, 8), 256, 0, st>>>(m2ec, dec_W, nullptr, nullptr, nullptr, nullptr,
            decc, BTQ, 1024, ENCD, ENCD, ENCD, 1024, 0);
        ola_kernel<<<dim3(NSAMP / 256, CHB), 256, 0, st>>>(decc, outc);
    }

    // ---- join ----
    cudaEventRecord(g_ctx.e_join, g_ctx.s1);
    cudaStreamWaitEvent((cudaStream_t)0, g_ctx.e_join, 0);
}

// round 17
// speedup vs baseline: 1.1860x; 1.1860x over previous
#include <cuda_runtime.h>
#include <cstdint>

#define NSAMP 256000
#define BATCH 64
#define NCHUNK 4
#define CHB (BATCH / NCHUNK)    // 16 batches per chunk
#define TT 997
#define BT (BATCH * TT)         // 63808
#define BTQ (CHB * TT)          // 15952
#define NFREQ 513
#define MAGP 528                // mag padded stride (33*16)
#define KSPEC 1040              // spec/gmat padded stride (65*16), data cols 0..1025
#define ENCD 256
#define EPS32 1.1920928955078125e-07f
#define PI_F 3.14159265358979323846f

// ---------------- scratch (device globals; allocation-free rule; zero-initialized) ------
__device__ float g_mag [(size_t)BT * MAGP];
__device__ float g_Rm  [(size_t)BT * NFREQ];
__device__ float g_Imb [(size_t)BT * NFREQ];
__device__ float g_xg  [(size_t)BT * 512];
__device__ float g_h1  [(size_t)BT * 128];
__device__ float g_h2  [(size_t)BT * 128];
__device__ float g_spec[(size_t)BT * KSPEC];   // [Sr(513) | Si(513) | pad] per row
__device__ float g_enc [(size_t)BT * ENCD];
__device__ float g_encn[(size_t)BT * ENCD];
__device__ float g_m2e [(size_t)BT * ENCD];
__device__ float g_dec [(size_t)BT * 1024];
__device__ float g_w1p [512 * MAGP];
__device__ float g_gmat[256 * KSPEC];          // [w*Gr/1024 | w*Gi/1024 | 0] per enc row

// ---------------- streams/events (created at load, before harness baseline) -------------
struct GpuCtx {
    cudaStream_t s[NCHUNK - 1];
    cudaEvent_t e_fork;
    cudaEvent_t e_join[NCHUNK - 1];
    GpuCtx() {
        for (int i = 0; i < NCHUNK - 1; i++) {
            cudaStreamCreateWithFlags(&s[i], cudaStreamNonBlocking);
            cudaEventCreateWithFlags(&e_join[i], cudaEventDisableTiming);
        }
        cudaEventCreateWithFlags(&e_fork, cudaEventDisableTiming);
    }
};
static GpuCtx g_ctx;

__device__ __forceinline__ float sigm(float x) { return 1.0f / (1.0f + __expf(-x)); }
__device__ __forceinline__ float tanh_f(float x) { return 2.0f / (1.0f + __expf(-2.0f * x)) - 1.0f; }

// ---------------- cp.async helpers ----------------
__device__ __forceinline__ void cp16(uint32_t dst, const void* src) {
    asm volatile("cp.async.cg.shared.global [%0], [%1], 16;" :: "r"(dst), "l"(src));
}
#define CP_COMMIT() asm volatile("cp.async.commit_group;" ::: "memory")
#define CP_WAIT(n)  asm volatile("cp.async.wait_group %0;" :: "n"(n) : "memory")

// ---------------- 2-term bf16 split of a float2: f = hi + lo (packed bf16x2) ------------
__device__ __forceinline__ void bf16x2split(float2 f, uint32_t& hi, uint32_t& lo) {
    uint32_t h;
    asm("cvt.rn.bf16x2.f32 %0, %1, %2;" : "=r"(h) : "f"(f.y), "f"(f.x));
    float rx = f.x - __uint_as_float(h << 16);
    float ry = f.y - __uint_as_float(h & 0xffff0000u);
    asm("cvt.rn.bf16x2.f32 %0, %1, %2;" : "=r"(lo) : "f"(ry), "f"(rx));
    hi = h;
}
__device__ __forceinline__ void mma16(float* c, const uint32_t* a, const uint32_t* b) {
    asm volatile(
        "mma.sync.aligned.m16n8k16.row.col.f32.bf16.bf16.f32 "
        "{%0,%1,%2,%3}, {%4,%5,%6,%7}, {%8,%9}, {%0,%1,%2,%3};"
        : "+f"(c[0]), "+f"(c[1]), "+f"(c[2]), "+f"(c[3])
        : "r"(a[0]), "r"(a[1]), "r"(a[2]), "r"(a[3]), "r"(b[0]), "r"(b[1]));
}

// ---------------- packed f32x2 fma ----------------
__device__ __forceinline__ unsigned long long fma2(unsigned long long a, unsigned long long b,
                                                   unsigned long long c) {
    unsigned long long d;
    asm("fma.rn.f32x2 %0, %1, %2, %3;" : "=l"(d) : "l"(a), "l"(b), "l"(c));
    return d;
}

// ---------------- 2xBF16 tensor-core GEMM: C[M,N] = A[M,K] @ W[N,K]^T --------------------
// MODE 0: + b1 + b2 (nullable). MODE 1: sigmoid(+b1). MODE 2: sigmoid(+b1)*aux[m,n].
// MODE 3: v=sigmoid(+b1); C[m,n]=v*aux[m,n]; C[m,513+n]=v*aux2[m,n]  (masked spectrum)
// Per K=16 slice: bf16 hi/lo split, 3 x m16n8k16 MMAs (hh, hl, lh). Requires K % 16 == 0.
#define SSTRIDE 20
template<int MODE>
__global__ void __launch_bounds__(256) gemm_mma(
    const float* __restrict__ A, const float* __restrict__ W,
    const float* __restrict__ b1, const float* __restrict__ b2,
    const float* __restrict__ aux, const float* __restrict__ aux2,
    float* __restrict__ C,
    int M, int N, int K, int lda, int ldw, int ldc, int ldaux)
{
    __shared__ float As[2][128 * SSTRIDE];
    __shared__ float Bs[2][128 * SSTRIDE];
    int tid = threadIdx.x;
    int lane = tid & 31;
    int wid = tid >> 5;
    int wm = wid & 3;
    int wn = wid >> 2;
    int m0 = blockIdx.x * 128, n0 = blockIdx.y * 128;

    int lr = tid >> 1;
    int lc0 = (tid & 1) * 2;
    const float* Arow = A + (size_t)min(m0 + lr, M - 1) * lda;
    const float* Wrow = W + (size_t)min(n0 + lr, N - 1) * ldw;

    uint32_t sA0 = (uint32_t)__cvta_generic_to_shared(&As[0][0]);
    uint32_t sB0 = (uint32_t)__cvta_generic_to_shared(&Bs[0][0]);
    const uint32_t stageBytes = 128 * SSTRIDE * 4;
    uint32_t dstOffA = (lr * SSTRIDE + lc0 * 4) * 4;

    #define LOAD_STAGE(t, s) do { \
        uint32_t dA = sA0 + (s) * stageBytes + dstOffA; \
        uint32_t dB = sB0 + (s) * stageBytes + dstOffA; \
        int f0 = (t) * 16 + lc0 * 4; \
        cp16(dA,      Arow + f0); \
        cp16(dA + 16, Arow + f0 + 4); \
        cp16(dB,      Wrow + f0); \
        cp16(dB + 16, Wrow + f0 + 4); \
        CP_COMMIT(); \
    } while (0)

    float c[2][8][4];
    #pragma unroll
    for (int mi = 0; mi < 2; mi++)
        #pragma unroll
        for (int j = 0; j < 8; j++)
            #pragma unroll
            for (int r = 0; r < 4; r++) c[mi][j][r] = 0.0f;

    const int NT = K >> 4;
    LOAD_STAGE(0, 0);

    int g = lane >> 2, q = lane & 3;
    int arow0 = (wm * 32 + g) * (SSTRIDE / 2) + q;   // float2 index
    int brow0 = (wn * 64 + g) * (SSTRIDE / 2) + q;

    for (int t = 0; t < NT; t++) {
        int buf = t & 1;
        if (t + 1 < NT) {
            LOAD_STAGE(t + 1, (t + 1) & 1);
            CP_WAIT(1);
        } else {
            CP_WAIT(0);
        }
        __syncthreads();

        const float2* Sa2 = (const float2*)As[buf];
        const float2* Sb2 = (const float2*)Bs[buf];
        uint32_t ah[2][4], al[2][4];
        #pragma unroll
        for (int mi = 0; mi < 2; mi++) {
            int i0 = arow0 + mi * 16 * (SSTRIDE / 2);
            bf16x2split(Sa2[i0],                        ah[mi][0], al[mi][0]);  // (g,   k0..1)
            bf16x2split(Sa2[i0 + 8 * (SSTRIDE / 2)],    ah[mi][1], al[mi][1]);  // (g+8, k0..1)
            bf16x2split(Sa2[i0 + 4],                    ah[mi][2], al[mi][2]);  // (g,   k8..9)
            bf16x2split(Sa2[i0 + 8 * (SSTRIDE / 2) + 4],ah[mi][3], al[mi][3]);  // (g+8, k8..9)
        }
        uint32_t bh[8][2], bl[8][2];
        #pragma unroll
        for (int j = 0; j < 8; j++) {
            int i0 = brow0 + j * 8 * (SSTRIDE / 2);
            bf16x2split(Sb2[i0],     bh[j][0], bl[j][0]);
            bf16x2split(Sb2[i0 + 4], bh[j][1], bl[j][1]);
        }
        #pragma unroll
        for (int mi = 0; mi < 2; mi++)
            #pragma unroll
            for (int j = 0; j < 8; j++) {
                mma16(c[mi][j], ah[mi], bl[j]);   // hi*lo
                mma16(c[mi][j], al[mi], bh[j]);   // lo*hi
                mma16(c[mi][j], ah[mi], bh[j]);   // hi*hi
            }
        __syncthreads();
    }

    #pragma unroll
    for (int mi = 0; mi < 2; mi++) {
        #pragma unroll
        for (int rh = 0; rh < 2; rh++) {
            int m = m0 + wm * 32 + mi * 16 + g + rh * 8;
            if (m >= M) continue;
            float* crow = C + (size_t)m * ldc;
            const float* arow  = (MODE >= 2) ? aux  + (size_t)m * ldaux : nullptr;
            const float* arow2 = (MODE == 3) ? aux2 + (size_t)m * ldaux : nullptr;
            #pragma unroll
            for (int j = 0; j < 8; j++) {
                int n = n0 + wn * 64 + j * 8 + 2 * q;
                float v0 = c[mi][j][rh * 2];
                float v1 = c[mi][j][rh * 2 + 1];
                if (MODE == 0) {
                    if (b1) { v0 += __ldg(&b1[n]); v1 += __ldg(&b1[n + 1]); }
                    if (b2) { v0 += __ldg(&b2[n]); v1 += __ldg(&b2[n + 1]); }
                    if (n < N)     crow[n]     = v0;
                    if (n + 1 < N) crow[n + 1] = v1;
                } else if (MODE == 1) {
                    if (n < N)     crow[n]     = sigm(v0 + __ldg(&b1[n]));
                    if (n + 1 < N) crow[n + 1] = sigm(v1 + __ldg(&b1[n + 1]));
                } else if (MODE == 2) {
                    if (n < N)     crow[n]     = sigm(v0 + __ldg(&b1[n]))     * arow[n];
                    if (n + 1 < N) crow[n + 1] = sigm(v1 + __ldg(&b1[n + 1])) * arow[n + 1];
                } else {
                    if (n < N) {
                        float s0 = sigm(v0 + __ldg(&b1[n]));
                        crow[n]       = s0 * arow[n];
                        crow[513 + n] = s0 * arow2[n];
                    }
                    if (n + 1 < N) {
                        float s1 = sigm(v1 + __ldg(&b1[n + 1]));
                        crow[n + 1]       = s1 * arow[n + 1];
                        crow[513 + n + 1] = s1 * arow2[n + 1];
                    }
                }
            }
        }
    }
    #undef LOAD_STAGE
}

// ---------------- weight pack: s1_Wih1 [512,513] -> [512,528] zero-padded ----------------
__global__ void pack_w1(const float* __restrict__ w, float* __restrict__ out) {
    int i = blockIdx.x * 256 + threadIdx.x;
    if (i < 512 * MAGP) {
        int r = i / MAGP, c = i - r * MAGP;
        out[i] = (c < NFREQ) ? w[r * NFREQ + c] : 0.0f;
    }
}

// ---------------- 512-pt complex Stockham FFT (table-driven twiddles) ----------------
__device__ __forceinline__ void build_tw(float2* tw, int tid, int nthr) {
    for (int m = tid; m <= 512; m += nthr) {
        float s, c;
        __sincosf(PI_F * (float)m * (1.0f / 512.0f), &s, &c);
        tw[m] = make_float2(c, -s);
    }
}
__device__ __forceinline__ float2* fft512(float2* a, float2* b, const float2* tw,
                                          bool fwd, int tid) {
    float2* src = a; float2* dst = b;
    #pragma unroll
    for (int s = 0; s < 9; s++) {
        int m = 1 << s;
        int j = tid >> s;
        int k = tid & (m - 1);
        float2 w = tw[j << (s + 1)];
        float wc = w.x;
        float ws = fwd ? w.y : -w.y;
        float2 c0 = src[tid];
        float2 c1 = src[tid + 256];
        float2 dif = make_float2(c0.x - c1.x, c0.y - c1.y);
        dst[2 * j * m + k]     = make_float2(c0.x + c1.x, c0.y + c1.y);
        dst[2 * j * m + k + m] = make_float2(wc * dif.x - ws * dif.y, wc * dif.y + ws * dif.x);
        __syncthreads();
        float2* t = src; src = dst; dst = t;
    }
    return src;
}

// ---------------- STFT (chunk of CHB batches) ----------------
__global__ void stft_kernel(const float* __restrict__ x, float* __restrict__ mag,
                            float* __restrict__ Rm, float* __restrict__ Imb) {
    __shared__ float2 za[512], zb[512];
    __shared__ float2 tw[513];
    int bt = blockIdx.x;
    int b = bt / TT, t = bt - b * TT;
    const float* xp = x + (size_t)b * NSAMP + t * 256;
    int tid = threadIdx.x;
    build_tw(tw, tid, 256);
    __syncthreads();
    for (int n = tid; n < 512; n += 256) {
        int i0 = 2 * n, i1 = 2 * n + 1;
        float c0 = tw[(i0 <= 512) ? i0 : 1024 - i0].x;
        float c1 = tw[(i1 <= 512) ? i1 : 1024 - i1].x;
        za[n] = make_float2(xp[i0] * (0.5f * (1.0f - c0)), xp[i1] * (0.5f * (1.0f - c1)));
    }
    __syncthreads();
    float2* Z = fft512(za, zb, tw, true, tid);
    size_t baseM = (size_t)bt * MAGP;
    size_t base = (size_t)bt * NFREQ;
    for (int k = tid; k <= 512; k += 256) {
        float2 zk = Z[k & 511];
        float2 zc = Z[(512 - k) & 511];
        float Er = 0.5f * (zk.x + zc.x), Ei = 0.5f * (zk.y - zc.y);
        float Or = 0.5f * (zk.y + zc.y), Oi = -0.5f * (zk.x - zc.x);
        float2 w = tw[k];
        float wc = w.x, ws = w.y;
        float Xr = Er + wc * Or - ws * Oi;
        float Xi = Ei + wc * Oi + ws * Or;
        float mg = sqrtf(fmaxf(Xr * Xr + Xi * Xi, EPS32));
        float rp = Xr + EPS32, ip = Xi + EPS32;
        float inv = rsqrtf(rp * rp + ip * ip);
        mag[baseM + k] = mg;
        Rm[base + k]   = mg * rp * inv;
        Imb[base + k]  = mg * ip * inv;
    }
    if (tid < MAGP - NFREQ) mag[baseM + NFREQ + tid] = 0.0f;
}

// ---------------- G-matrix precompute: gmat[e,:] = [w*Gr/1024 | w*Gi/1024 | 0] ----------
__global__ void prep_gmat(const float* __restrict__ encW, float* __restrict__ gmat) {
    __shared__ float2 za[512], zb[512];
    __shared__ float2 tw[513];
    int e = blockIdx.x;
    int tid = threadIdx.x;
    const float* wr = encW + (size_t)e * 1024;
    build_tw(tw, tid, 256);
    for (int n = tid; n < 512; n += 256)
        za[n] = make_float2(wr[2 * n], wr[2 * n + 1]);
    __syncthreads();
    float2* Z = fft512(za, zb, tw, true, tid);
    float* grow = gmat + (size_t)e * KSPEC;
    for (int k = tid; k <= 512; k += 256) {
        float2 zk = Z[k & 511];
        float2 zc = Z[(512 - k) & 511];
        float Er = 0.5f * (zk.x + zc.x), Ei = 0.5f * (zk.y - zc.y);
        float Or = 0.5f * (zk.y + zc.y), Oi = -0.5f * (zk.x - zc.x);
        float2 w = tw[k];
        float wc = w.x, ws = w.y;
        float Gr = Er + wc * Or - ws * Oi;
        float Gi = Ei + wc * Oi + ws * Or;
        float scale = ((k == 0) || (k == 512)) ? (1.0f / 1024.0f) : (2.0f / 1024.0f);
        grow[k]       = Gr * scale;
        grow[513 + k] = Gi * scale;
    }
    if (tid < KSPEC - 1026) grow[1026 + tid] = 0.0f;
}

// ---------------- LSTM scan (chunk): quad-gate, f32x2 FMA, 96 weight cols in regs -------
__global__ void __launch_bounds__(512) lstm_kernel(
    const float* __restrict__ xg, float* __restrict__ hout,
    const float* __restrict__ Whh, const float* __restrict__ state, int layer, int b0) {
    extern __shared__ float sm[];
    ulonglong2* Wsm = (ulonglong2*)sm;       // [8][512]: cols 96..127
    float* h_s = sm + 8 * 512 * 4;           // 2 x 128 floats (ping-pong)
    int b = blockIdx.x, t = threadIdx.x;
    int cell = t >> 2, gate = t & 3;
    int row = gate * 128 + cell;
    const unsigned long long* wr8 = (const unsigned long long*)(Whh + (size_t)row * 128);
    unsigned long long w2[48];
    #pragma unroll
    for (int p = 0; p < 48; p++) w2[p] = __ldg(&wr8[p]);
    #pragma unroll
    for (int g = 0; g < 8; g++) {
        const ulonglong2* p = (const ulonglong2*)(Whh + (size_t)row * 128 + 96 + g * 4);
        Wsm[g * 512 + t] = *p;
    }
    float cv;
    {
        size_t sb = ((size_t)(layer * BATCH + b0 + b) * 128 + cell) * 2;
        cv = state[sb + 1];
        if (gate == 0) h_s[cell] = state[sb];
    }
    __syncthreads();
    const float* xr = xg + (size_t)b * TT * 512 + row;
    float* hr = hout + (size_t)b * TT * 128;
    int lane = t & 31;
    int q = lane & ~3;
    float xcur = __ldg(xr);
    for (int tt = 0; tt < TT; tt++) {
        float xnext = (tt + 1 < TT) ? __ldg(xr + (tt + 1) * 512) : 0.0f;
        const ulonglong2* h2 = (const ulonglong2*)(h_s + (tt & 1) * 128);
        unsigned long long acc0, acc1;
        asm("mov.b64 %0, {%1,%2};" : "=l"(acc0) : "f"(xcur), "f"(0.0f));
        asm("mov.b64 %0, {%1,%2};" : "=l"(acc1) : "f"(0.0f), "f"(0.0f));
        #pragma unroll
        for (int g = 0; g < 24; g++) {
            ulonglong2 hv = h2[g];
            acc0 = fma2(w2[2 * g],     hv.x, acc0);
            acc1 = fma2(w2[2 * g + 1], hv.y, acc1);
        }
        #pragma unroll
        for (int g = 0; g < 8; g++) {
            ulonglong2 wv = Wsm[g * 512 + t];
            ulonglong2 hv = h2[24 + g];
            acc0 = fma2(wv.x, hv.x, acc0);
            acc1 = fma2(wv.y, hv.y, acc1);
        }
        float a0, a1, a2, a3;
        asm("mov.b64 {%0,%1}, %2;" : "=f"(a0), "=f"(a1) : "l"(acc0));
        asm("mov.b64 {%0,%1}, %2;" : "=f"(a2), "=f"(a3) : "l"(acc1));
        float acc = (a0 + a2) + (a1 + a3);
        float v = (gate == 2) ? tanh_f(acc) : sigm(acc);
        float iv = __shfl_sync(0xffffffffu, v, q + 0);
        float fv = __shfl_sync(0xffffffffu, v, q + 1);
        float gv = __shfl_sync(0xffffffffu, v, q + 2);
        float ov = __shfl_sync(0xffffffffu, v, q + 3);
        cv = fv * cv + iv * gv;
        float hv = ov * tanh_f(cv);
        if (gate == 0) {
            h_s[((tt + 1) & 1) * 128 + cell] = hv;
            hr[tt * 128 + cell] = hv;
        }
        __syncthreads();
        xcur = xnext;
    }
}

// ---------------- instant layernorm over last dim (256) ----------------
__global__ void iln_kernel(const float* __restrict__ enc, const float* __restrict__ gamma,
                           const float* __restrict__ beta, float* __restrict__ out) {
    int bt = blockIdx.x, tid = threadIdx.x;
    float v = enc[(size_t)bt * ENCD + tid];
    float s1 = v, s2 = v * v;
    #pragma unroll
    for (int o = 16; o > 0; o >>= 1) {
        s1 += __shfl_xor_sync(0xffffffff, s1, o);
        s2 += __shfl_xor_sync(0xffffffff, s2, o);
    }
    __shared__ float r1[8], r2[8];
    int wid = tid >> 5;
    if ((tid & 31) == 0) { r1[wid] = s1; r2[wid] = s2; }
    __syncthreads();
    if (tid == 0) {
        float a1 = 0.0f, a2 = 0.0f;
        #pragma unroll
        for (int i = 0; i < 8; i++) { a1 += r1[i]; a2 += r2[i]; }
        r1[0] = a1; r2[0] = a2;
    }
    __syncthreads();
    float mean = r1[0] * (1.0f / 256.0f);
    float var  = r2[0] * (1.0f / 256.0f) - mean * mean;
    out[(size_t)bt * ENCD + tid] =
        (v - mean) * rsqrtf(var + 1e-7f) * gamma[tid] + beta[tid];
}

// ---------------- overlap-add (chunk of CHB batches) ----------------
__global__ void ola_kernel(const float* __restrict__ dec, float* __restrict__ out) {
    int s = blockIdx.x * 256 + threadIdx.x;
    int b = blockIdx.y;
    int thi = min(TT - 1, s >> 8);
    int tlo = (s >= 1024) ? ((s - 1023 + 255) >> 8) : 0;
    float acc = 0.0f;
    for (int t = tlo; t <= thi; t++)
        acc += dec[((size_t)b * TT + t) * 1024 + (s - (t << 8))];
    out[(size_t)b * NSAMP + s] = acc;
}

// ---------------- host ----------------
extern "C" void kernel_launch(void* const* d_in, const int* in_sizes, int n_in,
                              void* d_out, int out_size) {
    const float* x        = (const float*)d_in[0];
    const float* st1      = (const float*)d_in[1];
    const float* st2      = (const float*)d_in[2];
    const float* s1_Wih1  = (const float*)d_in[3];
    const float* s1_Whh1  = (const float*)d_in[4];
    const float* s1_bih1  = (const float*)d_in[5];
    const float* s1_bhh1  = (const float*)d_in[6];
    const float* s1_Wih2  = (const float*)d_in[7];
    const float* s1_Whh2  = (const float*)d_in[8];
    const float* s1_bih2  = (const float*)d_in[9];
    const float* s1_bhh2  = (const float*)d_in[10];
    const float* s1_Wd    = (const float*)d_in[11];
    const float* s1_bd    = (const float*)d_in[12];
    const float* s2_Wih1  = (const float*)d_in[13];
    const float* s2_Whh1  = (const float*)d_in[14];
    const float* s2_bih1  = (const float*)d_in[15];
    const float* s2_bhh1  = (const float*)d_in[16];
    const float* s2_Wih2  = (const float*)d_in[17];
    const float* s2_Whh2  = (const float*)d_in[18];
    const float* s2_bih2  = (const float*)d_in[19];
    const float* s2_bhh2  = (const float*)d_in[20];
    const float* s2_Wd    = (const float*)d_in[21];
    const float* s2_bd    = (const float*)d_in[22];
    const float* enc_W    = (const float*)d_in[23];
    const float* dec_W    = (const float*)d_in[24];
    const float* gamma    = (const float*)d_in[25];
    const float* beta     = (const float*)d_in[26];
    float* out = (float*)d_out;

    float *mag, *Rm, *Imb, *xg, *h1, *h2, *spec, *enc, *encn, *m2e, *dec, *w1p, *gmat;
    cudaGetSymbolAddress((void**)&mag,   g_mag);
    cudaGetSymbolAddress((void**)&Rm,    g_Rm);
    cudaGetSymbolAddress((void**)&Imb,   g_Imb);
    cudaGetSymbolAddress((void**)&xg,    g_xg);
    cudaGetSymbolAddress((void**)&h1,    g_h1);
    cudaGetSymbolAddress((void**)&h2,    g_h2);
    cudaGetSymbolAddress((void**)&spec,  g_spec);
    cudaGetSymbolAddress((void**)&enc,   g_enc);
    cudaGetSymbolAddress((void**)&encn,  g_encn);
    cudaGetSymbolAddress((void**)&m2e,   g_m2e);
    cudaGetSymbolAddress((void**)&dec,   g_dec);
    cudaGetSymbolAddress((void**)&w1p,   g_w1p);
    cudaGetSymbolAddress((void**)&gmat,  g_gmat);

    const int LSTM_SMEM = 8 * 512 * 16 + 2 * 128 * 4;  // 66,560 B
    cudaFuncSetAttribute(lstm_kernel, cudaFuncAttributeMaxDynamicSharedMemorySize, LSTM_SMEM);

    const int MTQ = (BTQ + 127) / 128;  // 125

    // ---- shared prologue on origin stream, then fork ----
    pack_w1<<<(512 * MAGP + 255) / 256, 256>>>(s1_Wih1, w1p);
    prep_gmat<<<256, 256>>>(enc_W, gmat);
    cudaEventRecord(g_ctx.e_fork, 0);
    for (int i = 0; i < NCHUNK - 1; i++)
        cudaStreamWaitEvent(g_ctx.s[i], g_ctx.e_fork, 0);

    for (int c = 0; c < NCHUNK; c++) {
        cudaStream_t st = (c == 0) ? (cudaStream_t)0 : g_ctx.s[c - 1];
        int b0 = c * CHB;
        const float* xc = x + (size_t)b0 * NSAMP;
        float* magc   = mag   + (size_t)c * BTQ * MAGP;
        float* Rmc    = Rm    + (size_t)c * BTQ * NFREQ;
        float* Imc    = Imb   + (size_t)c * BTQ * NFREQ;
        float* xgc    = xg    + (size_t)c * BTQ * 512;
        float* h1c    = h1    + (size_t)c * BTQ * 128;
        float* h2c    = h2    + (size_t)c * BTQ * 128;
        float* specc  = spec  + (size_t)c * BTQ * KSPEC;
        float* encc   = enc   + (size_t)c * BTQ * ENCD;
        float* encnc  = encn  + (size_t)c * BTQ * ENCD;
        float* m2ec   = m2e   + (size_t)c * BTQ * ENCD;
        float* decc   = dec   + (size_t)c * BTQ * 1024;
        float* outc   = out   + (size_t)b0 * NSAMP;

        stft_kernel<<<BTQ, 256, 0, st>>>(xc, magc, Rmc, Imc);

        gemm_mma<0><<<dim3(MTQ, 4), 256, 0, st>>>(magc, w1p, s1_bih1, s1_bhh1, nullptr, nullptr,
            xgc, BTQ, 512, MAGP, MAGP, MAGP, 512, 0);
        lstm_kernel<<<CHB, 512, LSTM_SMEM, st>>>(xgc, h1c, s1_Whh1, st1, 0, b0);
        gemm_mma<0><<<dim3(MTQ, 4), 256, 0, st>>>(h1c, s1_Wih2, s1_bih2, s1_bhh2, nullptr, nullptr,
            xgc, BTQ, 512, 128, 128, 128, 512, 0);
        lstm_kernel<<<CHB, 512, LSTM_SMEM, st>>>(xgc, h2c, s1_Whh2, st1, 1, b0);
        gemm_mma<3><<<dim3(MTQ, 5), 256, 0, st>>>(h2c, s1_Wd, s1_bd, nullptr, Rmc, Imc,
            specc, BTQ, NFREQ, 128, 128, 128, KSPEC, NFREQ);

        gemm_mma<0><<<dim3(MTQ, 2), 256, 0, st>>>(specc, gmat, nullptr, nullptr, nullptr, nullptr,
            encc, BTQ, ENCD, KSPEC, KSPEC, KSPEC, ENCD, 0);
        iln_kernel<<<BTQ, 256, 0, st>>>(encc, gamma, beta, encnc);

        gemm_mma<0><<<dim3(MTQ, 4), 256, 0, st>>>(encnc, s2_Wih1, s2_bih1, s2_bhh1, nullptr, nullptr,
            xgc, BTQ, 512, ENCD, ENCD, ENCD, 512, 0);
        lstm_kernel<<<CHB, 512, LSTM_SMEM, st>>>(xgc, h1c, s2_Whh1, st2, 0, b0);
        gemm_mma<0><<<dim3(MTQ, 4), 256, 0, st>>>(h1c, s2_Wih2, s2_bih2, s2_bhh2, nullptr, nullptr,
            xgc, BTQ, 512, 128, 128, 128, 512, 0);
        lstm_kernel<<<CHB, 512, LSTM_SMEM, st>>>(xgc, h2c, s2_Whh2, st2, 1, b0);
        gemm_mma<2><<<dim3(MTQ, 2), 256, 0, st>>>(h2c, s2_Wd, s2_bd, nullptr, encc, nullptr,
            m2ec, BTQ, ENCD, 128, 128, 128, ENCD, ENCD);

        gemm_mma<0><<<dim3(MTQ, 8), 256, 0, st>>>(m2ec, dec_W, nullptr, nullptr, nullptr, nullptr,
            decc, BTQ, 1024, ENCD, ENCD, ENCD, 1024, 0);
        ola_kernel<<<dim3(NSAMP / 256, CHB), 256, 0, st>>>(decc, outc);
    }

    // ---- join ----
    for (int i = 0; i < NCHUNK - 1; i++) {
        cudaEventRecord(g_ctx.e_join[i], g_ctx.s[i]);
        cudaStreamWaitEvent((cudaStream_t)0, g_ctx.e_join[i], 0);
    }
}